// round 4
// baseline (speedup 1.0000x reference)
#include <cuda_runtime.h>
#include <cuda_bf16.h>
#include <cstdint>

// -------- scratch (device globals; no allocation allowed) --------
#define NMAX 100000
#define EMAX 1600000
#define NB_MAX 128            // ceil(NMAX/1024) = 98 <= 128

__device__ __align__(16) float g_h[(size_t)NMAX * 32];   // hidden features
__device__ int g_src32[EMAX];
__device__ int g_dst32[EMAX];
__device__ int g_rowptr[NMAX + 1];
__device__ int g_cnt[NMAX];        // degree counts
__device__ int g_cursor[NMAX];     // fill cursors
__device__ int g_csr_src[EMAX];    // src ids grouped by dst
__device__ int g_bsum[NB_MAX];
__device__ int g_boff[NB_MAX];
__device__ int g_is64;

// -------- sniff edge-index dtype: int64 iff all sampled odd words are zero --------
__global__ void sniff_kernel(const unsigned int* __restrict__ w, int nsamples) {
    int nz = 0;
    for (int i = threadIdx.x; i < nsamples; i += blockDim.x)
        nz |= (w[2 * i + 1] != 0u) ? 1 : 0;
    nz = __syncthreads_or(nz);
    if (threadIdx.x == 0) g_is64 = nz ? 0 : 1;
}

// -------- convert edge index (either dtype) to int32 src/dst arrays --------
__global__ void convert_kernel(const void* __restrict__ ei,
                               int* __restrict__ s32, int* __restrict__ d32,
                               int E) {
    int is64 = g_is64;
    int stride = gridDim.x * blockDim.x;
    if (is64) {
        const long long* p = (const long long*)ei;
        for (int e = blockIdx.x * blockDim.x + threadIdx.x; e < E; e += stride) {
            s32[e] = (int)p[e];
            d32[e] = (int)p[e + E];
        }
    } else {
        const int* p = (const int*)ei;
        for (int e = blockIdx.x * blockDim.x + threadIdx.x; e < E; e += stride) {
            s32[e] = p[e];
            d32[e] = p[e + E];
        }
    }
}

// -------- zero int --------
__global__ void zero_int_kernel(int* __restrict__ a, int n) {
    int i = blockIdx.x * blockDim.x + threadIdx.x;
    if (i < n) a[i] = 0;
}

// -------- count in-degree --------
__global__ void count_kernel(const int* __restrict__ dst,
                             int* __restrict__ cnt, int E, int N) {
    int stride = gridDim.x * blockDim.x;
    for (int e = blockIdx.x * blockDim.x + threadIdx.x; e < E; e += stride) {
        int d = dst[e];
        if (d >= 0 && d < N) atomicAdd(&cnt[d], 1);
    }
}

// -------- scan stage 1: per-1024-block inclusive scan -> exclusive + block totals --------
__global__ void scan1_kernel(const int* __restrict__ cnt,
                             int* __restrict__ rowptr,
                             int* __restrict__ bsum, int N) {
    __shared__ int sh[1024];
    int gid = blockIdx.x * 1024 + threadIdx.x;
    int v = (gid < N) ? cnt[gid] : 0;
    sh[threadIdx.x] = v;
    __syncthreads();
    for (int off = 1; off < 1024; off <<= 1) {
        int t = (threadIdx.x >= off) ? sh[threadIdx.x - off] : 0;
        __syncthreads();
        sh[threadIdx.x] += t;
        __syncthreads();
    }
    if (gid < N) rowptr[gid] = sh[threadIdx.x] - v;   // exclusive
    if (threadIdx.x == 1023) bsum[blockIdx.x] = sh[1023];
}

// -------- scan stage 2: scan block totals (single block) --------
__global__ void scan2_kernel(const int* __restrict__ bsum,
                             int* __restrict__ boff, int nb,
                             int* __restrict__ rowptr, int N, int E) {
    __shared__ int sh[NB_MAX];
    int v = (threadIdx.x < nb) ? bsum[threadIdx.x] : 0;
    sh[threadIdx.x] = v;
    __syncthreads();
    for (int off = 1; off < NB_MAX; off <<= 1) {
        int t = (threadIdx.x >= off) ? sh[threadIdx.x - off] : 0;
        __syncthreads();
        sh[threadIdx.x] += t;
        __syncthreads();
    }
    if (threadIdx.x < nb) boff[threadIdx.x] = sh[threadIdx.x] - v;  // exclusive
    if (threadIdx.x == 0) rowptr[N] = E;
}

// -------- scan stage 3: add block offsets; zero cursors --------
__global__ void scan3_kernel(int* __restrict__ rowptr,
                             const int* __restrict__ boff,
                             int* __restrict__ cursor, int N) {
    int gid = blockIdx.x * blockDim.x + threadIdx.x;
    if (gid < N) {
        rowptr[gid] += boff[gid >> 10];
        cursor[gid] = 0;
    }
}

// -------- fill CSR: csr_src holds src ids grouped by dst --------
__global__ void fill_kernel(const int* __restrict__ src,
                            const int* __restrict__ dst,
                            const int* __restrict__ rowptr,
                            int* __restrict__ cursor,
                            int* __restrict__ csr_src, int E, int N) {
    int stride = gridDim.x * blockDim.x;
    for (int e = blockIdx.x * blockDim.x + threadIdx.x; e < E; e += stride) {
        int d = dst[e];
        if (d < 0 || d >= N) continue;
        int pos = atomicAdd(&cursor[d], 1);
        int idx = rowptr[d] + pos;
        if (idx >= 0 && idx < E) csr_src[idx] = src[e];
    }
}

// -------- fused layer: out = act( mean_{s in N(n)} xg[s] @ Wl + xs[n] @ Wr + b ) --------
// warp per node; lane = feature index (F_in = 32). Neighbor rows are coalesced
// 128B loads; W columns live in registers; rows broadcast via shfl.
template <int FOUT, bool RELU>
__global__ void sage_layer_kernel(const float* __restrict__ xg,
                                  const float* __restrict__ xs,
                                  const int* __restrict__ rowptr,
                                  const int* __restrict__ csr_src,
                                  const float* __restrict__ Wl,
                                  const float* __restrict__ Wr,
                                  const float* __restrict__ b,
                                  float* __restrict__ out, int N) {
    int lane = threadIdx.x & 31;
    int warp = (blockIdx.x * blockDim.x + threadIdx.x) >> 5;
    int nwarps = (gridDim.x * blockDim.x) >> 5;

    int j = (lane < FOUT) ? lane : 0;
    float wl[32], wr[32];
#pragma unroll
    for (int k = 0; k < 32; k++) {
        wl[k] = Wl[k * FOUT + j];
        wr[k] = Wr[k * FOUT + j];
    }
    float bj = b[j];

    for (int n = warp; n < N; n += nwarps) {
        int s0 = rowptr[n];
        int s1 = rowptr[n + 1];
        int deg = s1 - s0;

        float acc = 0.0f;
        for (int e0 = s0; e0 < s1; e0 += 32) {
            int cnt = min(32, s1 - e0);
            int sid = (lane < cnt) ? csr_src[e0 + lane] : 0;
            sid = min(max(sid, 0), N - 1);
            for (int k = 0; k < cnt; k++) {
                int s = __shfl_sync(0xffffffffu, sid, k);
                acc += xg[(size_t)s * 32 + lane];
            }
        }
        float inv = 1.0f / (float)max(deg, 1);
        float m = acc * inv;
        float xv = xs[(size_t)n * 32 + lane];

        float r = bj;
#pragma unroll
        for (int k = 0; k < 32; k++) {
            float mk = __shfl_sync(0xffffffffu, m, k);
            float xk = __shfl_sync(0xffffffffu, xv, k);
            r = fmaf(mk, wl[k], fmaf(xk, wr[k], r));
        }
        if (RELU) r = fmaxf(r, 0.0f);
        if (lane < FOUT) out[(size_t)n * FOUT + lane] = r;
    }
}

extern "C" void kernel_launch(void* const* d_in, const int* in_sizes, int n_in,
                              void* d_out, int out_size) {
    const float* x   = (const float*)d_in[0];
    const void*  ei  = d_in[1];
    const float* W1l = (const float*)d_in[2];
    const float* W1r = (const float*)d_in[3];
    const float* b1  = (const float*)d_in[4];
    const float* W2l = (const float*)d_in[5];
    const float* W2r = (const float*)d_in[6];
    const float* b2  = (const float*)d_in[7];
    float* out = (float*)d_out;

    int N = in_sizes[0] / 32;   // 100000
    int E = in_sizes[1] / 2;    // 1600000

    float* h;
    int *src32, *dst32, *rowptr, *cnt, *cursor, *csr_src, *bsum, *boff;
    cudaGetSymbolAddress((void**)&h, g_h);
    cudaGetSymbolAddress((void**)&src32, g_src32);
    cudaGetSymbolAddress((void**)&dst32, g_dst32);
    cudaGetSymbolAddress((void**)&rowptr, g_rowptr);
    cudaGetSymbolAddress((void**)&cnt, g_cnt);
    cudaGetSymbolAddress((void**)&cursor, g_cursor);
    cudaGetSymbolAddress((void**)&csr_src, g_csr_src);
    cudaGetSymbolAddress((void**)&bsum, g_bsum);
    cudaGetSymbolAddress((void**)&boff, g_boff);

    int nb = (N + 1023) / 1024;           // 98

    // ---- dtype sniff + edge conversion ----
    sniff_kernel<<<1, 256>>>((const unsigned int*)ei, 4096);
    convert_kernel<<<2048, 256>>>(ei, src32, dst32, E);

    // ---- CSR build (once; shared by both layers) ----
    zero_int_kernel<<<(N + 255) / 256, 256>>>(cnt, N);
    count_kernel<<<2048, 256>>>(dst32, cnt, E, N);
    scan1_kernel<<<nb, 1024>>>(cnt, rowptr, bsum, N);
    scan2_kernel<<<1, NB_MAX>>>(bsum, boff, nb, rowptr, N, E);
    scan3_kernel<<<(N + 255) / 256, 256>>>(rowptr, boff, cursor, N);
    fill_kernel<<<2048, 256>>>(src32, dst32, rowptr, cursor, csr_src, E, N);

    // ---- layer 1: h = relu(sage(x)) ----
    sage_layer_kernel<32, true><<<2048, 256>>>(x, x, rowptr, csr_src,
                                               W1l, W1r, b1, h, N);
    // ---- layer 2: out = sage(h) ----
    sage_layer_kernel<16, false><<<2048, 256>>>(h, h, rowptr, csr_src,
                                                W2l, W2r, b2, out, N);
}

// round 5
// speedup vs baseline: 1.2268x; 1.2268x over previous
#include <cuda_runtime.h>
#include <cuda_bf16.h>
#include <cstdint>

// -------- scratch (device globals; no allocation allowed) --------
#define NMAX 100000
#define EMAX 1600000
#define NB_MAX 128            // ceil(NMAX/1024) = 98 <= 128

__device__ __align__(16) float g_h[(size_t)NMAX * 32];   // hidden features
__device__ __align__(16) float g_z2[(size_t)NMAX * 16];  // h @ W2l
__device__ __align__(16) float g_r2[(size_t)NMAX * 16];  // h @ W2r + b2
__device__ int g_rowptr[NMAX + 1];
__device__ int g_cnt[NMAX];
__device__ int g_cursor[NMAX];
__device__ int g_csr_src[EMAX];
__device__ int g_bsum[NB_MAX];
__device__ int g_boff[NB_MAX];
__device__ int g_is64;

// -------- sniff edge-index dtype: int64 iff all sampled odd words are zero --------
__global__ void sniff_kernel(const unsigned int* __restrict__ w, int nsamples) {
    int nz = 0;
    for (int i = threadIdx.x; i < nsamples; i += blockDim.x)
        nz |= (w[2 * i + 1] != 0u) ? 1 : 0;
    nz = __syncthreads_or(nz);
    if (threadIdx.x == 0) g_is64 = nz ? 0 : 1;
}

// -------- zero int --------
__global__ void zero_int_kernel(int* __restrict__ a, int n) {
    int i = blockIdx.x * blockDim.x + threadIdx.x;
    if (i < n) a[i] = 0;
}

// -------- count in-degree, reading edge index directly (either dtype) --------
__global__ void count_kernel(const void* __restrict__ ei,
                             int* __restrict__ cnt, int E, int N) {
    int is64 = g_is64;
    int stride = gridDim.x * blockDim.x;
    if (is64) {
        const long long* p = (const long long*)ei + E;  // dst row
        for (int e = blockIdx.x * blockDim.x + threadIdx.x; e < E; e += stride) {
            int d = (int)p[e];
            if (d >= 0 && d < N) atomicAdd(&cnt[d], 1);
        }
    } else {
        const int* p = (const int*)ei + E;
        for (int e = blockIdx.x * blockDim.x + threadIdx.x; e < E; e += stride) {
            int d = p[e];
            if (d >= 0 && d < N) atomicAdd(&cnt[d], 1);
        }
    }
}

// -------- scan stage 1 --------
__global__ void scan1_kernel(const int* __restrict__ cnt,
                             int* __restrict__ rowptr,
                             int* __restrict__ bsum, int N) {
    __shared__ int sh[1024];
    int gid = blockIdx.x * 1024 + threadIdx.x;
    int v = (gid < N) ? cnt[gid] : 0;
    sh[threadIdx.x] = v;
    __syncthreads();
    for (int off = 1; off < 1024; off <<= 1) {
        int t = (threadIdx.x >= off) ? sh[threadIdx.x - off] : 0;
        __syncthreads();
        sh[threadIdx.x] += t;
        __syncthreads();
    }
    if (gid < N) rowptr[gid] = sh[threadIdx.x] - v;   // exclusive
    if (threadIdx.x == 1023) bsum[blockIdx.x] = sh[1023];
}

// -------- scan stage 2 --------
__global__ void scan2_kernel(const int* __restrict__ bsum,
                             int* __restrict__ boff, int nb,
                             int* __restrict__ rowptr, int N, int E) {
    __shared__ int sh[NB_MAX];
    int v = (threadIdx.x < nb) ? bsum[threadIdx.x] : 0;
    sh[threadIdx.x] = v;
    __syncthreads();
    for (int off = 1; off < NB_MAX; off <<= 1) {
        int t = (threadIdx.x >= off) ? sh[threadIdx.x - off] : 0;
        __syncthreads();
        sh[threadIdx.x] += t;
        __syncthreads();
    }
    if (threadIdx.x < nb) boff[threadIdx.x] = sh[threadIdx.x] - v;
    if (threadIdx.x == 0) rowptr[N] = E;
}

// -------- scan stage 3: add block offsets; zero cursors --------
__global__ void scan3_kernel(int* __restrict__ rowptr,
                             const int* __restrict__ boff,
                             int* __restrict__ cursor, int N) {
    int gid = blockIdx.x * blockDim.x + threadIdx.x;
    if (gid < N) {
        rowptr[gid] += boff[gid >> 10];
        cursor[gid] = 0;
    }
}

// -------- fill CSR directly from edge index --------
__global__ void fill_kernel(const void* __restrict__ ei,
                            const int* __restrict__ rowptr,
                            int* __restrict__ cursor,
                            int* __restrict__ csr_src, int E, int N) {
    int is64 = g_is64;
    int stride = gridDim.x * blockDim.x;
    for (int e = blockIdx.x * blockDim.x + threadIdx.x; e < E; e += stride) {
        int s, d;
        if (is64) {
            const long long* p = (const long long*)ei;
            s = (int)p[e]; d = (int)p[e + E];
        } else {
            const int* p = (const int*)ei;
            s = p[e]; d = p[e + E];
        }
        if (d < 0 || d >= N) continue;
        int pos = atomicAdd(&cursor[d], 1);
        int idx = rowptr[d] + pos;
        if (idx >= 0 && idx < E) csr_src[idx] = s;
    }
}

// -------- layer 1 (fused): h = relu( mean_{s} x[s] @ W1l + x[n] @ W1r + b1 ) --------
// warp per node; lane = feature (32). Neighbor rows = coalesced 128B loads.
__global__ void sage_layer1_kernel(const float* __restrict__ x,
                                   const int* __restrict__ rowptr,
                                   const int* __restrict__ csr_src,
                                   const float* __restrict__ Wl,
                                   const float* __restrict__ Wr,
                                   const float* __restrict__ b,
                                   float* __restrict__ out, int N) {
    int lane = threadIdx.x & 31;
    int warp = (blockIdx.x * blockDim.x + threadIdx.x) >> 5;
    int nwarps = (gridDim.x * blockDim.x) >> 5;

    float wl[32], wr[32];
#pragma unroll
    for (int k = 0; k < 32; k++) {
        wl[k] = Wl[k * 32 + lane];
        wr[k] = Wr[k * 32 + lane];
    }
    float bj = b[lane];

    for (int n = warp; n < N; n += nwarps) {
        int s0 = rowptr[n];
        int s1 = rowptr[n + 1];
        int deg = s1 - s0;

        float acc = 0.0f;
        for (int e0 = s0; e0 < s1; e0 += 32) {
            int cnt = min(32, s1 - e0);
            int sid = (lane < cnt) ? csr_src[e0 + lane] : 0;
            sid = min(max(sid, 0), N - 1);
            for (int k = 0; k < cnt; k++) {
                int s = __shfl_sync(0xffffffffu, sid, k);
                acc += x[(size_t)s * 32 + lane];
            }
        }
        float m = acc * (1.0f / (float)max(deg, 1));
        float xv = x[(size_t)n * 32 + lane];

        float r = bj;
#pragma unroll
        for (int k = 0; k < 32; k++) {
            float mk = __shfl_sync(0xffffffffu, m, k);
            float xk = __shfl_sync(0xffffffffu, xv, k);
            r = fmaf(mk, wl[k], fmaf(xk, wr[k], r));
        }
        r = fmaxf(r, 0.0f);
        out[(size_t)n * 32 + lane] = r;
    }
}

// -------- layer-2 transform: z2 = h @ W2l ; r2 = h @ W2r + b2 (per node, once) --------
// warp per node; lanes 0-15 own W2l columns, lanes 16-31 own W2r columns.
__global__ void xform2_kernel(const float* __restrict__ h,
                              const float* __restrict__ W2l,
                              const float* __restrict__ W2r,
                              const float* __restrict__ b2,
                              float* __restrict__ z2,
                              float* __restrict__ r2, int N) {
    int lane = threadIdx.x & 31;
    int warp = (blockIdx.x * blockDim.x + threadIdx.x) >> 5;
    int nwarps = (gridDim.x * blockDim.x) >> 5;

    int j = lane & 15;
    bool left = lane < 16;
    float w[32];
#pragma unroll
    for (int k = 0; k < 32; k++)
        w[k] = left ? W2l[k * 16 + j] : W2r[k * 16 + j];
    float bj = left ? 0.0f : b2[j];

    for (int n = warp; n < N; n += nwarps) {
        float hv = h[(size_t)n * 32 + lane];
        float acc = bj;
#pragma unroll
        for (int k = 0; k < 32; k++) {
            float hk = __shfl_sync(0xffffffffu, hv, k);
            acc = fmaf(hk, w[k], acc);
        }
        if (left) z2[(size_t)n * 16 + j] = acc;
        else      r2[(size_t)n * 16 + j] = acc;
    }
}

// -------- layer-2 aggregate: out[n] = mean_{s} z2[s] + r2[n]  (F=16) --------
// warp handles 2 nodes: half-warp per node, lane = (half<<4)|feat.
__global__ void layer2_agg_kernel(const float* __restrict__ z2,
                                  const float* __restrict__ r2,
                                  const int* __restrict__ rowptr,
                                  const int* __restrict__ csr_src,
                                  float* __restrict__ out, int N) {
    int lane = threadIdx.x & 31;
    int half = lane >> 4;
    int f = lane & 15;
    int warp = (blockIdx.x * blockDim.x + threadIdx.x) >> 5;
    int nwarps = (gridDim.x * blockDim.x) >> 5;
    int npairs = N >> 1;   // N = 100000 even

    for (int pair = warp; pair < npairs; pair += nwarps) {
        int n = pair * 2 + half;
        int s0 = rowptr[n];
        int s1 = rowptr[n + 1];
        int deg = s1 - s0;

        int nch = (deg + 15) >> 4;
        int mx = max(nch, __shfl_xor_sync(0xffffffffu, nch, 16));

        float acc = 0.0f;
        for (int c = 0; c < mx; c++) {
            int base = s0 + c * 16;
            int cnt = min(16, s1 - base);       // may be <= 0
            int sid = (f < cnt) ? csr_src[base + f] : 0;
            sid = min(max(sid, 0), N - 1);
#pragma unroll
            for (int k = 0; k < 16; k++) {
                int s = __shfl_sync(0xffffffffu, sid, (half << 4) | k);
                float v = z2[(size_t)s * 16 + f];
                acc += (k < cnt) ? v : 0.0f;
            }
        }
        float m = acc * (1.0f / (float)max(deg, 1));
        out[(size_t)n * 16 + f] = m + r2[(size_t)n * 16 + f];
    }
}

extern "C" void kernel_launch(void* const* d_in, const int* in_sizes, int n_in,
                              void* d_out, int out_size) {
    const float* x   = (const float*)d_in[0];
    const void*  ei  = d_in[1];
    const float* W1l = (const float*)d_in[2];
    const float* W1r = (const float*)d_in[3];
    const float* b1  = (const float*)d_in[4];
    const float* W2l = (const float*)d_in[5];
    const float* W2r = (const float*)d_in[6];
    const float* b2  = (const float*)d_in[7];
    float* out = (float*)d_out;

    int N = in_sizes[0] / 32;   // 100000
    int E = in_sizes[1] / 2;    // 1600000

    float *h, *z2, *r2;
    int *rowptr, *cnt, *cursor, *csr_src, *bsum, *boff;
    cudaGetSymbolAddress((void**)&h, g_h);
    cudaGetSymbolAddress((void**)&z2, g_z2);
    cudaGetSymbolAddress((void**)&r2, g_r2);
    cudaGetSymbolAddress((void**)&rowptr, g_rowptr);
    cudaGetSymbolAddress((void**)&cnt, g_cnt);
    cudaGetSymbolAddress((void**)&cursor, g_cursor);
    cudaGetSymbolAddress((void**)&csr_src, g_csr_src);
    cudaGetSymbolAddress((void**)&bsum, g_bsum);
    cudaGetSymbolAddress((void**)&boff, g_boff);

    int nb = (N + 1023) / 1024;           // 98

    // ---- dtype sniff ----
    sniff_kernel<<<1, 256>>>((const unsigned int*)ei, 4096);

    // ---- CSR build (shared by both layers) ----
    zero_int_kernel<<<(N + 255) / 256, 256>>>(cnt, N);
    count_kernel<<<2048, 256>>>(ei, cnt, E, N);
    scan1_kernel<<<nb, 1024>>>(cnt, rowptr, bsum, N);
    scan2_kernel<<<1, NB_MAX>>>(bsum, boff, nb, rowptr, N, E);
    scan3_kernel<<<(N + 255) / 256, 256>>>(rowptr, boff, cursor, N);
    fill_kernel<<<2048, 256>>>(ei, rowptr, cursor, csr_src, E, N);

    // ---- layer 1 ----
    sage_layer1_kernel<<<2048, 256>>>(x, rowptr, csr_src, W1l, W1r, b1, h, N);

    // ---- layer 2: transform first (halves gather traffic), then aggregate ----
    xform2_kernel<<<1024, 256>>>(h, W2l, W2r, b2, z2, r2, N);
    layer2_agg_kernel<<<2048, 256>>>(z2, r2, rowptr, csr_src, out, N);
}

// round 7
// speedup vs baseline: 1.2904x; 1.0518x over previous
#include <cuda_runtime.h>
#include <cuda_bf16.h>
#include <cstdint>

// -------- scratch (device globals; no allocation allowed) --------
#define NMAX 100000
#define EMAX 1600000
#define NB_MAX 128            // ceil(NMAX/1024) = 98 <= 128

__device__ __align__(16) float g_h[(size_t)NMAX * 32];   // hidden features
__device__ __align__(16) float g_z2[(size_t)NMAX * 16];  // h @ W2l
__device__ __align__(16) float g_r2[(size_t)NMAX * 16];  // h @ W2r + b2
__device__ int g_rowptr[NMAX + 1];
__device__ int g_cnt[NMAX];
__device__ int g_cursor[NMAX];
__device__ int g_csr_src[EMAX];
__device__ int g_bsum[NB_MAX];
__device__ int g_is64;

// -------- zero cnt + sniff dtype (block 0) --------
__global__ void zero_sniff_kernel(int* __restrict__ cnt, int n,
                                  const unsigned int* __restrict__ w,
                                  int nsamples) {
    int i = blockIdx.x * blockDim.x + threadIdx.x;
    if (i < n) cnt[i] = 0;
    if (blockIdx.x == 0) {
        int nz = 0;
        for (int k = threadIdx.x; k < nsamples; k += blockDim.x)
            nz |= (w[2 * k + 1] != 0u) ? 1 : 0;
        nz = __syncthreads_or(nz);
        if (threadIdx.x == 0) g_is64 = nz ? 0 : 1;
    }
}

// -------- count in-degree (vectorized pair reads) --------
__global__ void count_kernel(const void* __restrict__ ei,
                             int* __restrict__ cnt, int E, int N) {
    int is64 = g_is64;
    int stride = gridDim.x * blockDim.x;
    int P = E >> 1;   // E even
    if (is64) {
        const longlong2* p = (const longlong2*)((const long long*)ei + E);
        for (int i = blockIdx.x * blockDim.x + threadIdx.x; i < P; i += stride) {
            longlong2 v = p[i];
            int d0 = (int)v.x, d1 = (int)v.y;
            if (d0 >= 0 && d0 < N) atomicAdd(&cnt[d0], 1);
            if (d1 >= 0 && d1 < N) atomicAdd(&cnt[d1], 1);
        }
    } else {
        const int2* p = (const int2*)((const int*)ei + E);
        for (int i = blockIdx.x * blockDim.x + threadIdx.x; i < P; i += stride) {
            int2 v = p[i];
            if (v.x >= 0 && v.x < N) atomicAdd(&cnt[v.x], 1);
            if (v.y >= 0 && v.y < N) atomicAdd(&cnt[v.y], 1);
        }
    }
}

// -------- scan stage 1: per-1024-block exclusive scan + block totals --------
__global__ void scan1_kernel(const int* __restrict__ cnt,
                             int* __restrict__ rowptr,
                             int* __restrict__ bsum, int N) {
    __shared__ int sh[1024];
    int gid = blockIdx.x * 1024 + threadIdx.x;
    int v = (gid < N) ? cnt[gid] : 0;
    sh[threadIdx.x] = v;
    __syncthreads();
    for (int off = 1; off < 1024; off <<= 1) {
        int t = (threadIdx.x >= off) ? sh[threadIdx.x - off] : 0;
        __syncthreads();
        sh[threadIdx.x] += t;
        __syncthreads();
    }
    if (gid < N) rowptr[gid] = sh[threadIdx.x] - v;   // exclusive
    if (threadIdx.x == 1023) bsum[blockIdx.x] = sh[1023];
}

// -------- scan stage 2+3 fused: each block re-scans bsum locally --------
__global__ void scan23_kernel(int* __restrict__ rowptr,
                              const int* __restrict__ bsum,
                              int* __restrict__ cursor, int N, int E, int nb) {
    __shared__ int sh[NB_MAX];
    if (threadIdx.x < NB_MAX)
        sh[threadIdx.x] = (threadIdx.x < nb) ? bsum[threadIdx.x] : 0;
    __syncthreads();
    for (int off = 1; off < NB_MAX; off <<= 1) {
        int t = (threadIdx.x < NB_MAX && threadIdx.x >= off) ? sh[threadIdx.x - off] : 0;
        __syncthreads();
        if (threadIdx.x < NB_MAX) sh[threadIdx.x] += t;   // inclusive
        __syncthreads();
    }
    int gid = blockIdx.x * blockDim.x + threadIdx.x;
    if (gid < N) {
        int w = gid >> 10;
        rowptr[gid] += (w > 0) ? sh[w - 1] : 0;
        cursor[gid] = 0;
    }
    if (gid == 0) rowptr[N] = E;
}

// -------- fill CSR directly from edge index (vectorized pair reads) --------
__global__ void fill_kernel(const void* __restrict__ ei,
                            const int* __restrict__ rowptr,
                            int* __restrict__ cursor,
                            int* __restrict__ csr_src, int E, int N) {
    int is64 = g_is64;
    int stride = gridDim.x * blockDim.x;
    int P = E >> 1;
    if (is64) {
        const longlong2* ps = (const longlong2*)ei;
        const longlong2* pd = (const longlong2*)((const long long*)ei + E);
        for (int i = blockIdx.x * blockDim.x + threadIdx.x; i < P; i += stride) {
            longlong2 sv = ps[i], dv = pd[i];
            int s0 = (int)sv.x, s1 = (int)sv.y;
            int d0 = (int)dv.x, d1 = (int)dv.y;
            if (d0 >= 0 && d0 < N) {
                int pos = atomicAdd(&cursor[d0], 1);
                csr_src[rowptr[d0] + pos] = s0;
            }
            if (d1 >= 0 && d1 < N) {
                int pos = atomicAdd(&cursor[d1], 1);
                csr_src[rowptr[d1] + pos] = s1;
            }
        }
    } else {
        const int2* ps = (const int2*)ei;
        const int2* pd = (const int2*)((const int*)ei + E);
        for (int i = blockIdx.x * blockDim.x + threadIdx.x; i < P; i += stride) {
            int2 sv = ps[i], dv = pd[i];
            if (dv.x >= 0 && dv.x < N) {
                int pos = atomicAdd(&cursor[dv.x], 1);
                csr_src[rowptr[dv.x] + pos] = sv.x;
            }
            if (dv.y >= 0 && dv.y < N) {
                int pos = atomicAdd(&cursor[dv.y], 1);
                csr_src[rowptr[dv.y] + pos] = sv.y;
            }
        }
    }
}

// -------- layer 1 (fused): h = relu( mean_{s} x[s] @ W1l + x[n] @ W1r + b1 ) --------
// warp per node; lane = feature (32). cnt is warp-uniform here, so the
// cnt-dependent loop bounds are convergence-safe. 4 accumulators for MLP.
__global__ void sage_layer1_kernel(const float* __restrict__ x,
                                   const int* __restrict__ rowptr,
                                   const int* __restrict__ csr_src,
                                   const float* __restrict__ Wl,
                                   const float* __restrict__ Wr,
                                   const float* __restrict__ b,
                                   float* __restrict__ out, int N) {
    int lane = threadIdx.x & 31;
    int warp = (blockIdx.x * blockDim.x + threadIdx.x) >> 5;
    int nwarps = (gridDim.x * blockDim.x) >> 5;

    float wl[32], wr[32];
#pragma unroll
    for (int k = 0; k < 32; k++) {
        wl[k] = Wl[k * 32 + lane];
        wr[k] = Wr[k * 32 + lane];
    }
    float bj = b[lane];

    for (int n = warp; n < N; n += nwarps) {
        int s0 = rowptr[n];
        int s1 = rowptr[n + 1];
        int deg = s1 - s0;

        float a0 = 0.f, a1 = 0.f, a2 = 0.f, a3 = 0.f;
        for (int e0 = s0; e0 < s1; e0 += 32) {
            int cnt = min(32, s1 - e0);            // warp-uniform
            int sid = (lane < cnt) ? csr_src[e0 + lane] : 0;
            int k = 0;
            for (; k + 4 <= cnt; k += 4) {
                int i0 = __shfl_sync(0xffffffffu, sid, k);
                int i1 = __shfl_sync(0xffffffffu, sid, k + 1);
                int i2 = __shfl_sync(0xffffffffu, sid, k + 2);
                int i3 = __shfl_sync(0xffffffffu, sid, k + 3);
                a0 += x[(size_t)i0 * 32 + lane];
                a1 += x[(size_t)i1 * 32 + lane];
                a2 += x[(size_t)i2 * 32 + lane];
                a3 += x[(size_t)i3 * 32 + lane];
            }
            for (; k < cnt; k++) {
                int i0 = __shfl_sync(0xffffffffu, sid, k);
                a0 += x[(size_t)i0 * 32 + lane];
            }
        }
        float m = ((a0 + a1) + (a2 + a3)) * (1.0f / (float)max(deg, 1));
        float xv = x[(size_t)n * 32 + lane];

        float r = bj;
#pragma unroll
        for (int k = 0; k < 32; k++) {
            float mk = __shfl_sync(0xffffffffu, m, k);
            float xk = __shfl_sync(0xffffffffu, xv, k);
            r = fmaf(mk, wl[k], fmaf(xk, wr[k], r));
        }
        r = fmaxf(r, 0.0f);
        out[(size_t)n * 32 + lane] = r;
    }
}

// -------- layer-2 transform: z2 = h @ W2l ; r2 = h @ W2r + b2 --------
__global__ void xform2_kernel(const float* __restrict__ h,
                              const float* __restrict__ W2l,
                              const float* __restrict__ W2r,
                              const float* __restrict__ b2,
                              float* __restrict__ z2,
                              float* __restrict__ r2, int N) {
    int lane = threadIdx.x & 31;
    int warp = (blockIdx.x * blockDim.x + threadIdx.x) >> 5;
    int nwarps = (gridDim.x * blockDim.x) >> 5;

    int j = lane & 15;
    bool left = lane < 16;
    float w[32];
#pragma unroll
    for (int k = 0; k < 32; k++)
        w[k] = left ? W2l[k * 16 + j] : W2r[k * 16 + j];
    float bj = left ? 0.0f : b2[j];

    for (int n = warp; n < N; n += nwarps) {
        float hv = h[(size_t)n * 32 + lane];
        float acc = bj;
#pragma unroll
        for (int k = 0; k < 32; k++) {
            float hk = __shfl_sync(0xffffffffu, hv, k);
            acc = fmaf(hk, w[k], acc);
        }
        if (left) z2[(size_t)n * 16 + j] = acc;
        else      r2[(size_t)n * 16 + j] = acc;
    }
}

// -------- layer-2 aggregate: out[n] = mean_{s} z2[s] + r2[n]  (F=16) --------
// warp handles 2 nodes (half-warp each). ALL shfl-bearing loop bounds are
// warp-uniform (max over the two halves); per-half tails are predicated.
__global__ void layer2_agg_kernel(const float* __restrict__ z2,
                                  const float* __restrict__ r2,
                                  const int* __restrict__ rowptr,
                                  const int* __restrict__ csr_src,
                                  float* __restrict__ out, int N) {
    int lane = threadIdx.x & 31;
    int half = lane >> 4;
    int f = lane & 15;
    int hb = half << 4;
    int warp = (blockIdx.x * blockDim.x + threadIdx.x) >> 5;
    int nwarps = (gridDim.x * blockDim.x) >> 5;
    int npairs = N >> 1;   // N even

    for (int pair = warp; pair < npairs; pair += nwarps) {
        int n = pair * 2 + half;
        int s0 = rowptr[n];
        int s1 = rowptr[n + 1];
        int deg = s1 - s0;

        int nch = (deg + 15) >> 4;
        int mx = max(nch, __shfl_xor_sync(0xffffffffu, nch, 16));  // warp-uniform

        float a0 = 0.f, a1 = 0.f, a2 = 0.f, a3 = 0.f;
        for (int c = 0; c < mx; c++) {
            int base = s0 + c * 16;
            int cnt = min(16, s1 - base);                      // per-half, may be <= 0
            int cu = max(cnt, __shfl_xor_sync(0xffffffffu, cnt, 16));  // warp-uniform
            int sid = (f < cnt) ? csr_src[base + f] : 0;
            for (int k = 0; k < cu; k += 4) {                  // uniform trip count
                int i0 = __shfl_sync(0xffffffffu, sid, hb | k);
                int i1 = __shfl_sync(0xffffffffu, sid, hb | ((k + 1) & 15));
                int i2 = __shfl_sync(0xffffffffu, sid, hb | ((k + 2) & 15));
                int i3 = __shfl_sync(0xffffffffu, sid, hb | ((k + 3) & 15));
                float v0 = z2[(size_t)i0 * 16 + f];
                float v1 = z2[(size_t)i1 * 16 + f];
                float v2 = z2[(size_t)i2 * 16 + f];
                float v3 = z2[(size_t)i3 * 16 + f];
                a0 += (k     < cnt) ? v0 : 0.0f;
                a1 += (k + 1 < cnt) ? v1 : 0.0f;
                a2 += (k + 2 < cnt) ? v2 : 0.0f;
                a3 += (k + 3 < cnt) ? v3 : 0.0f;
            }
        }
        float m = ((a0 + a1) + (a2 + a3)) * (1.0f / (float)max(deg, 1));
        out[(size_t)n * 16 + f] = m + r2[(size_t)n * 16 + f];
    }
}

extern "C" void kernel_launch(void* const* d_in, const int* in_sizes, int n_in,
                              void* d_out, int out_size) {
    const float* x   = (const float*)d_in[0];
    const void*  ei  = d_in[1];
    const float* W1l = (const float*)d_in[2];
    const float* W1r = (const float*)d_in[3];
    const float* b1  = (const float*)d_in[4];
    const float* W2l = (const float*)d_in[5];
    const float* W2r = (const float*)d_in[6];
    const float* b2  = (const float*)d_in[7];
    float* out = (float*)d_out;

    int N = in_sizes[0] / 32;   // 100000
    int E = in_sizes[1] / 2;    // 1600000

    float *h, *z2, *r2;
    int *rowptr, *cnt, *cursor, *csr_src, *bsum;
    cudaGetSymbolAddress((void**)&h, g_h);
    cudaGetSymbolAddress((void**)&z2, g_z2);
    cudaGetSymbolAddress((void**)&r2, g_r2);
    cudaGetSymbolAddress((void**)&rowptr, g_rowptr);
    cudaGetSymbolAddress((void**)&cnt, g_cnt);
    cudaGetSymbolAddress((void**)&cursor, g_cursor);
    cudaGetSymbolAddress((void**)&csr_src, g_csr_src);
    cudaGetSymbolAddress((void**)&bsum, g_bsum);

    int nb = (N + 1023) / 1024;           // 98

    // 1: zero cnt + sniff dtype
    zero_sniff_kernel<<<(N + 255) / 256, 256>>>(cnt, N, (const unsigned int*)ei, 4096);
    // 2: count in-degree
    count_kernel<<<2048, 256>>>(ei, cnt, E, N);
    // 3: block-level scan
    scan1_kernel<<<nb, 1024>>>(cnt, rowptr, bsum, N);
    // 4: finalize rowptr + zero cursors
    scan23_kernel<<<(N + 255) / 256, 256>>>(rowptr, bsum, cursor, N, E, nb);
    // 5: fill CSR
    fill_kernel<<<2048, 256>>>(ei, rowptr, cursor, csr_src, E, N);
    // 6: layer 1 (profiled slot: -s 5)
    sage_layer1_kernel<<<2048, 256>>>(x, rowptr, csr_src, W1l, W1r, b1, h, N);
    // 7: layer-2 transform
    xform2_kernel<<<1024, 256>>>(h, W2l, W2r, b2, z2, r2, N);
    // 8: layer-2 aggregate
    layer2_agg_kernel<<<2048, 256>>>(z2, r2, rowptr, csr_src, out, N);
}

// round 8
// speedup vs baseline: 1.8302x; 1.4183x over previous
#include <cuda_runtime.h>
#include <cuda_bf16.h>
#include <cstdint>

// -------- scratch (device globals; no allocation allowed) --------
#define NMAX 100000
#define EMAX 1600000
#define NB_MAX 128            // ceil(NMAX/1024) = 98 <= 128

__device__ __align__(16) float g_mean[(size_t)NMAX * 32]; // mean of neighbor x rows
__device__ __align__(16) float g_z2[(size_t)NMAX * 16];   // h @ W2l
__device__ __align__(16) float g_r2[(size_t)NMAX * 16];   // h @ W2r + b2
__device__ int g_rowptr[NMAX + 1];
__device__ int g_cnt[NMAX];
__device__ int g_cursor[NMAX];
__device__ int g_csr_src[EMAX];
__device__ int g_bsum[NB_MAX];
__device__ int g_is64;

// -------- zero cnt + sniff dtype (block 0) --------
__global__ void zero_sniff_kernel(int* __restrict__ cnt, int n,
                                  const unsigned int* __restrict__ w,
                                  int nsamples) {
    int i = blockIdx.x * blockDim.x + threadIdx.x;
    if (i < n) cnt[i] = 0;
    if (blockIdx.x == 0) {
        int nz = 0;
        for (int k = threadIdx.x; k < nsamples; k += blockDim.x)
            nz |= (w[2 * k + 1] != 0u) ? 1 : 0;
        nz = __syncthreads_or(nz);
        if (threadIdx.x == 0) g_is64 = nz ? 0 : 1;
    }
}

// -------- count in-degree (vectorized pair reads) --------
__global__ void count_kernel(const void* __restrict__ ei,
                             int* __restrict__ cnt, int E, int N) {
    int is64 = g_is64;
    int stride = gridDim.x * blockDim.x;
    int P = E >> 1;   // E even
    if (is64) {
        const longlong2* p = (const longlong2*)((const long long*)ei + E);
        for (int i = blockIdx.x * blockDim.x + threadIdx.x; i < P; i += stride) {
            longlong2 v = p[i];
            int d0 = (int)v.x, d1 = (int)v.y;
            if (d0 >= 0 && d0 < N) atomicAdd(&cnt[d0], 1);
            if (d1 >= 0 && d1 < N) atomicAdd(&cnt[d1], 1);
        }
    } else {
        const int2* p = (const int2*)((const int*)ei + E);
        for (int i = blockIdx.x * blockDim.x + threadIdx.x; i < P; i += stride) {
            int2 v = p[i];
            if (v.x >= 0 && v.x < N) atomicAdd(&cnt[v.x], 1);
            if (v.y >= 0 && v.y < N) atomicAdd(&cnt[v.y], 1);
        }
    }
}

// -------- scan stage 1: per-1024-block exclusive scan + block totals --------
__global__ void scan1_kernel(const int* __restrict__ cnt,
                             int* __restrict__ rowptr,
                             int* __restrict__ bsum, int N) {
    __shared__ int sh[1024];
    int gid = blockIdx.x * 1024 + threadIdx.x;
    int v = (gid < N) ? cnt[gid] : 0;
    sh[threadIdx.x] = v;
    __syncthreads();
    for (int off = 1; off < 1024; off <<= 1) {
        int t = (threadIdx.x >= off) ? sh[threadIdx.x - off] : 0;
        __syncthreads();
        sh[threadIdx.x] += t;
        __syncthreads();
    }
    if (gid < N) rowptr[gid] = sh[threadIdx.x] - v;   // exclusive
    if (threadIdx.x == 1023) bsum[blockIdx.x] = sh[1023];
}

// -------- scan stage 2+3 fused: each block re-scans bsum locally --------
__global__ void scan23_kernel(int* __restrict__ rowptr,
                              const int* __restrict__ bsum,
                              int* __restrict__ cursor, int N, int E, int nb) {
    __shared__ int sh[NB_MAX];
    if (threadIdx.x < NB_MAX)
        sh[threadIdx.x] = (threadIdx.x < nb) ? bsum[threadIdx.x] : 0;
    __syncthreads();
    for (int off = 1; off < NB_MAX; off <<= 1) {
        int t = (threadIdx.x < NB_MAX && threadIdx.x >= off) ? sh[threadIdx.x - off] : 0;
        __syncthreads();
        if (threadIdx.x < NB_MAX) sh[threadIdx.x] += t;   // inclusive
        __syncthreads();
    }
    int gid = blockIdx.x * blockDim.x + threadIdx.x;
    if (gid < N) {
        int w = gid >> 10;
        rowptr[gid] += (w > 0) ? sh[w - 1] : 0;
        cursor[gid] = 0;
    }
    if (gid == 0) rowptr[N] = E;
}

// -------- fill CSR directly from edge index (vectorized pair reads) --------
__global__ void fill_kernel(const void* __restrict__ ei,
                            const int* __restrict__ rowptr,
                            int* __restrict__ cursor,
                            int* __restrict__ csr_src, int E, int N) {
    int is64 = g_is64;
    int stride = gridDim.x * blockDim.x;
    int P = E >> 1;
    if (is64) {
        const longlong2* ps = (const longlong2*)ei;
        const longlong2* pd = (const longlong2*)((const long long*)ei + E);
        for (int i = blockIdx.x * blockDim.x + threadIdx.x; i < P; i += stride) {
            longlong2 sv = ps[i], dv = pd[i];
            int s0 = (int)sv.x, s1 = (int)sv.y;
            int d0 = (int)dv.x, d1 = (int)dv.y;
            if (d0 >= 0 && d0 < N) {
                int pos = atomicAdd(&cursor[d0], 1);
                csr_src[rowptr[d0] + pos] = s0;
            }
            if (d1 >= 0 && d1 < N) {
                int pos = atomicAdd(&cursor[d1], 1);
                csr_src[rowptr[d1] + pos] = s1;
            }
        }
    } else {
        const int2* ps = (const int2*)ei;
        const int2* pd = (const int2*)((const int*)ei + E);
        for (int i = blockIdx.x * blockDim.x + threadIdx.x; i < P; i += stride) {
            int2 sv = ps[i], dv = pd[i];
            if (dv.x >= 0 && dv.x < N) {
                int pos = atomicAdd(&cursor[dv.x], 1);
                csr_src[rowptr[dv.x] + pos] = sv.x;
            }
            if (dv.y >= 0 && dv.y < N) {
                int pos = atomicAdd(&cursor[dv.y], 1);
                csr_src[rowptr[dv.y] + pos] = sv.y;
            }
        }
    }
}

// -------- gather 1: mean[n] = (1/deg) * sum_{s in N(n)} x[s]   (rows 128B) --------
// Warp per node. 4 groups x 8 lanes; group g loads neighbor (e+g) as float4
// chunk c (lane = g*8+c). x2 unroll -> 8 rows in flight per warp.
__global__ void gather1_kernel(const float* __restrict__ x,
                               const int* __restrict__ rowptr,
                               const int* __restrict__ csr_src,
                               float* __restrict__ mean, int N) {
    int lane = threadIdx.x & 31;
    int g = lane >> 3;          // 0..3
    int c = lane & 7;           // 0..7
    int n = blockIdx.x * (blockDim.x >> 5) + (threadIdx.x >> 5);
    if (n >= N) return;

    int s0 = rowptr[n];
    int s1 = rowptr[n + 1];
    int deg = s1 - s0;

    float4 a0 = make_float4(0.f, 0.f, 0.f, 0.f);
    float4 a1 = make_float4(0.f, 0.f, 0.f, 0.f);
    for (int e = s0; e < s1; e += 8) {         // warp-uniform bound
        int i0 = e + g;
        int i1 = e + 4 + g;
        bool v0 = i0 < s1;
        bool v1 = i1 < s1;
        int sid0 = v0 ? csr_src[i0] : 0;
        int sid1 = v1 ? csr_src[i1] : 0;
        float4 r0 = ((const float4*)(x + (size_t)sid0 * 32))[c];
        float4 r1 = ((const float4*)(x + (size_t)sid1 * 32))[c];
        if (v0) { a0.x += r0.x; a0.y += r0.y; a0.z += r0.z; a0.w += r0.w; }
        if (v1) { a1.x += r1.x; a1.y += r1.y; a1.z += r1.z; a1.w += r1.w; }
    }
    a0.x += a1.x; a0.y += a1.y; a0.z += a1.z; a0.w += a1.w;
    // reduce across 4 groups (xor 8, 16)
#pragma unroll
    for (int s = 8; s <= 16; s <<= 1) {
        a0.x += __shfl_xor_sync(0xffffffffu, a0.x, s);
        a0.y += __shfl_xor_sync(0xffffffffu, a0.y, s);
        a0.z += __shfl_xor_sync(0xffffffffu, a0.z, s);
        a0.w += __shfl_xor_sync(0xffffffffu, a0.w, s);
    }
    if (g == 0) {
        float inv = 1.0f / (float)max(deg, 1);
        float4 m = make_float4(a0.x * inv, a0.y * inv, a0.z * inv, a0.w * inv);
        ((float4*)(mean + (size_t)n * 32))[c] = m;
    }
}

// -------- fused dense: h = relu(mean@W1l + x@W1r + b1); z2 = h@W2l; r2 = h@W2r + b2 --------
// Warp per node (grid-stride). lane = feature for layer 1; half-split for layer 2.
__global__ void dense_kernel(const float* __restrict__ x,
                             const float* __restrict__ mean,
                             const float* __restrict__ W1l,
                             const float* __restrict__ W1r,
                             const float* __restrict__ b1,
                             const float* __restrict__ W2l,
                             const float* __restrict__ W2r,
                             const float* __restrict__ b2,
                             float* __restrict__ z2,
                             float* __restrict__ r2, int N) {
    int lane = threadIdx.x & 31;
    int warp = (blockIdx.x * blockDim.x + threadIdx.x) >> 5;
    int nwarps = (gridDim.x * blockDim.x) >> 5;

    float wl1[32], wr1[32], w2[32];
#pragma unroll
    for (int k = 0; k < 32; k++) {
        wl1[k] = W1l[k * 32 + lane];
        wr1[k] = W1r[k * 32 + lane];
    }
    int j = lane & 15;
    bool left = lane < 16;
#pragma unroll
    for (int k = 0; k < 32; k++)
        w2[k] = left ? W2l[k * 16 + j] : W2r[k * 16 + j];
    float b1j = b1[lane];
    float b2j = left ? 0.0f : b2[j];

    for (int n = warp; n < N; n += nwarps) {
        float mv = mean[(size_t)n * 32 + lane];
        float xv = x[(size_t)n * 32 + lane];

        float r = b1j;
#pragma unroll
        for (int k = 0; k < 32; k++) {
            float mk = __shfl_sync(0xffffffffu, mv, k);
            float xk = __shfl_sync(0xffffffffu, xv, k);
            r = fmaf(mk, wl1[k], fmaf(xk, wr1[k], r));
        }
        float h = fmaxf(r, 0.0f);

        float acc = b2j;
#pragma unroll
        for (int k = 0; k < 32; k++) {
            float hk = __shfl_sync(0xffffffffu, h, k);
            acc = fmaf(hk, w2[k], acc);
        }
        if (left) z2[(size_t)n * 16 + j] = acc;
        else      r2[(size_t)n * 16 + j] = acc;
    }
}

// -------- gather 2: out[n] = (1/deg) * sum_{s} z2[s] + r2[n]   (rows 64B) --------
// Warp per node. 8 groups x 4 lanes; group g loads neighbor (e+g) as float4
// chunk c (lane = g*4+c). x2 unroll -> 16 rows in flight per warp.
__global__ void gather2_kernel(const float* __restrict__ z2,
                               const float* __restrict__ r2,
                               const int* __restrict__ rowptr,
                               const int* __restrict__ csr_src,
                               float* __restrict__ out, int N) {
    int lane = threadIdx.x & 31;
    int g = lane >> 2;          // 0..7
    int c = lane & 3;           // 0..3
    int n = blockIdx.x * (blockDim.x >> 5) + (threadIdx.x >> 5);
    if (n >= N) return;

    int s0 = rowptr[n];
    int s1 = rowptr[n + 1];
    int deg = s1 - s0;

    float4 a0 = make_float4(0.f, 0.f, 0.f, 0.f);
    float4 a1 = make_float4(0.f, 0.f, 0.f, 0.f);
    for (int e = s0; e < s1; e += 16) {        // warp-uniform bound
        int i0 = e + g;
        int i1 = e + 8 + g;
        bool v0 = i0 < s1;
        bool v1 = i1 < s1;
        int sid0 = v0 ? csr_src[i0] : 0;
        int sid1 = v1 ? csr_src[i1] : 0;
        float4 r0 = ((const float4*)(z2 + (size_t)sid0 * 16))[c];
        float4 r1 = ((const float4*)(z2 + (size_t)sid1 * 16))[c];
        if (v0) { a0.x += r0.x; a0.y += r0.y; a0.z += r0.z; a0.w += r0.w; }
        if (v1) { a1.x += r1.x; a1.y += r1.y; a1.z += r1.z; a1.w += r1.w; }
    }
    a0.x += a1.x; a0.y += a1.y; a0.z += a1.z; a0.w += a1.w;
#pragma unroll
    for (int s = 4; s <= 16; s <<= 1) {
        a0.x += __shfl_xor_sync(0xffffffffu, a0.x, s);
        a0.y += __shfl_xor_sync(0xffffffffu, a0.y, s);
        a0.z += __shfl_xor_sync(0xffffffffu, a0.z, s);
        a0.w += __shfl_xor_sync(0xffffffffu, a0.w, s);
    }
    if (g == 0) {
        float inv = 1.0f / (float)max(deg, 1);
        float4 rr = ((const float4*)(r2 + (size_t)n * 16))[c];
        float4 o = make_float4(a0.x * inv + rr.x, a0.y * inv + rr.y,
                               a0.z * inv + rr.z, a0.w * inv + rr.w);
        ((float4*)(out + (size_t)n * 16))[c] = o;
    }
}

extern "C" void kernel_launch(void* const* d_in, const int* in_sizes, int n_in,
                              void* d_out, int out_size) {
    const float* x   = (const float*)d_in[0];
    const void*  ei  = d_in[1];
    const float* W1l = (const float*)d_in[2];
    const float* W1r = (const float*)d_in[3];
    const float* b1  = (const float*)d_in[4];
    const float* W2l = (const float*)d_in[5];
    const float* W2r = (const float*)d_in[6];
    const float* b2  = (const float*)d_in[7];
    float* out = (float*)d_out;

    int N = in_sizes[0] / 32;   // 100000
    int E = in_sizes[1] / 2;    // 1600000

    float *mean, *z2, *r2;
    int *rowptr, *cnt, *cursor, *csr_src, *bsum;
    cudaGetSymbolAddress((void**)&mean, g_mean);
    cudaGetSymbolAddress((void**)&z2, g_z2);
    cudaGetSymbolAddress((void**)&r2, g_r2);
    cudaGetSymbolAddress((void**)&rowptr, g_rowptr);
    cudaGetSymbolAddress((void**)&cnt, g_cnt);
    cudaGetSymbolAddress((void**)&cursor, g_cursor);
    cudaGetSymbolAddress((void**)&csr_src, g_csr_src);
    cudaGetSymbolAddress((void**)&bsum, g_bsum);

    int nb = (N + 1023) / 1024;           // 98
    int gblocks = (N + 7) / 8;            // 8 warps per 256-thread block

    // ---- CSR build ----
    zero_sniff_kernel<<<(N + 255) / 256, 256>>>(cnt, N, (const unsigned int*)ei, 4096);
    count_kernel<<<2048, 256>>>(ei, cnt, E, N);
    scan1_kernel<<<nb, 1024>>>(cnt, rowptr, bsum, N);
    scan23_kernel<<<(N + 255) / 256, 256>>>(rowptr, bsum, cursor, N, E, nb);
    fill_kernel<<<2048, 256>>>(ei, rowptr, cursor, csr_src, E, N);

    // ---- layer 1 gather (pure, high-occupancy) ----
    gather1_kernel<<<gblocks, 256>>>(x, rowptr, csr_src, mean, N);
    // ---- fused dense: layer-1 linear+relu and layer-2 transform ----
    dense_kernel<<<2048, 256>>>(x, mean, W1l, W1r, b1, W2l, W2r, b2, z2, r2, N);
    // ---- layer 2 gather + epilogue ----
    gather2_kernel<<<gblocks, 256>>>(z2, r2, rowptr, csr_src, out, N);
}